// round 2
// baseline (speedup 1.0000x reference)
#include <cuda_runtime.h>

// Problem constants (fixed shapes: B=2, C=128, D=H=W=16)
#define NNODE 4096
#define CDIM  128
#define EDIM  46
#define GDIM  64
#define BCNT  2
#define PROJW 192   // theta(64) | phi(64) | G(64)

// ---------------- scratch (device globals; no allocation allowed) ----------
__device__ float g_h[BCNT * NNODE * CDIM];        // [B,N,C]
__device__ float g_proj[BCNT * NNODE * PROJW];    // [B,N,192]
__device__ float g_f[BCNT * NNODE * EDIM];        // [B,N,E]
__device__ float g_fp[NNODE * EDIM];              // [N,E] raw (unnormalized)
__device__ float g_pth[NNODE * 64];               // p_theta
__device__ float g_pph[NNODE * 64];               // p_phi
__device__ float g_ss[92 * 32];                   // [B*E] column sumsq, 128B stride
__device__ float g_ssfp[46 * 32];                 // [E] f_p column sumsq, 128B stride
__device__ float g_Wcat[PROJW * CDIM];
__device__ float g_bcat[PROJW];

// Closed-form sorted neighbor index (matches np.sort of the concatenated axes)
__device__ __forceinline__ int nbr_idx(int i, int j, int k, int e) {
    if (e < i) return (e << 8) | (j << 4) | k;          // ax0, i' < i
    int t = e - i;
    if (t < 31) {                                        // in-block (256*i .. +255)
        if (t < j)      return (i << 8) | (t << 4) | k;          // j' < j
        if (t < j + 16) return (i << 8) | (j << 4) | (t - j);    // k' sweep (incl self)
        return (i << 8) | ((t - 15) << 4) | k;                   // j' > j
    }
    return ((e - 30) << 8) | (j << 4) | k;              // ax0, i' > i
}

// ---------------- K0: transpose x [B,C,N] -> h [B,N,C] ---------------------
__global__ void k_tr(const float* __restrict__ x) {
    int idx = blockIdx.x * 256 + threadIdx.x;           // < 2^20
    int b = idx >> 19;
    int rem = idx & ((1 << 19) - 1);
    int n = rem >> 7;
    int c = rem & 127;
    g_h[idx] = x[(((b << 7) + c) << 12) + n];
}

// ---------------- K1: build Wcat/bcat, geo features, zero ssfp -------------
__global__ void k_prep(const float* __restrict__ Gw, const float* __restrict__ Gb,
                       const float* __restrict__ thw, const float* __restrict__ thb,
                       const float* __restrict__ phw, const float* __restrict__ phb,
                       const float* __restrict__ gthw, const float* __restrict__ gthb,
                       const float* __restrict__ gphw, const float* __restrict__ gphb) {
    int gtid = blockIdx.x * blockDim.x + threadIdx.x;
    int gs = gridDim.x * blockDim.x;

    for (int idx = gtid; idx < PROJW * CDIM; idx += gs) {
        int r = idx >> 7, k = idx & 127;
        float v = (r < 64) ? thw[r * 128 + k]
                 : (r < 128) ? phw[(r - 64) * 128 + k]
                 : Gw[(r - 128) * 128 + k];
        g_Wcat[idx] = v;
    }
    for (int idx = gtid; idx < PROJW; idx += gs)
        g_bcat[idx] = (idx < 64) ? thb[idx] : (idx < 128) ? phb[idx - 64] : Gb[idx - 128];
    for (int idx = gtid; idx < 46; idx += gs) g_ssfp[idx * 32] = 0.f;

    for (int idx = gtid; idx < NNODE * 64; idx += gs) {
        int n = idx >> 6, d = idx & 63;
        int i = n >> 8, j = (n >> 4) & 15, k = n & 15;
        float p0 = i * (1.f / 15.f) - 0.5f;
        float p1 = j * (1.f / 15.f) - 0.5f;
        float p2 = k * (1.f / 15.f) - 0.5f;
        g_pth[idx] = p0 * gthw[d * 3] + p1 * gthw[d * 3 + 1] + p2 * gthw[d * 3 + 2] + gthb[d];
        g_pph[idx] = p0 * gphw[d * 3] + p1 * gphw[d * 3 + 1] + p2 * gphw[d * 3 + 2] + gphb[d];
    }
}

// ---------------- K2: f_p raw + column sumsq -------------------------------
__global__ void k_fp() {
    int n = blockIdx.x;
    int tid = threadIdx.x;                 // blockDim = 64
    __shared__ float th[64];
    th[tid] = g_pth[n * 64 + tid];
    __syncthreads();
    if (tid < EDIM) {
        int i = n >> 8, j = (n >> 4) & 15, k = n & 15;
        int m = nbr_idx(i, j, k, tid);
        const float4* ph4 = reinterpret_cast<const float4*>(&g_pph[m * 64]);
        float acc = 0.f;
#pragma unroll
        for (int d = 0; d < 16; d++) {
            float4 v = ph4[d];
            acc += th[4 * d] * v.x + th[4 * d + 1] * v.y + th[4 * d + 2] * v.z + th[4 * d + 3] * v.w;
        }
        g_fp[n * EDIM + tid] = acc;
        atomicAdd(&g_ssfp[tid * 32], acc * acc);
    }
}

// ---------------- K3: fused projection GEMM [8192,128]@[128,192]+bias ------
// grid (128, 3), block 256. Also zeroes g_ss for this round's k_f atomics.
__global__ void k_proj() {
    __shared__ float As[64][33];
    __shared__ float Bs[32][68];
    int tid = threadIdx.x;
    if (blockIdx.x == 0 && blockIdx.y == 0 && tid < 92) g_ss[tid * 32] = 0.f;

    int rowBase = blockIdx.x * 64;
    int colBase = blockIdx.y * 64;
    int tx = tid & 15, ty = tid >> 4;
    float acc[4][4] = {};

    for (int k0 = 0; k0 < 128; k0 += 32) {
        for (int idx = tid; idx < 64 * 32; idx += 256) {
            int r = idx >> 5, kk = idx & 31;
            As[r][kk] = g_h[(rowBase + r) * 128 + k0 + kk];
        }
        for (int idx = tid; idx < 32 * 64; idx += 256) {
            int c = idx >> 5, kk = idx & 31;
            Bs[kk][c] = g_Wcat[(colBase + c) * 128 + k0 + kk];
        }
        __syncthreads();
#pragma unroll
        for (int kk = 0; kk < 32; kk++) {
            float a[4], bb[4];
#pragma unroll
            for (int i = 0; i < 4; i++) a[i] = As[ty * 4 + i][kk];
#pragma unroll
            for (int j = 0; j < 4; j++) bb[j] = Bs[kk][tx * 4 + j];
#pragma unroll
            for (int i = 0; i < 4; i++)
#pragma unroll
                for (int j = 0; j < 4; j++) acc[i][j] += a[i] * bb[j];
        }
        __syncthreads();
    }
#pragma unroll
    for (int i = 0; i < 4; i++) {
#pragma unroll
        for (int j = 0; j < 4; j++) {
            int c = colBase + tx * 4 + j;
            g_proj[(rowBase + ty * 4 + i) * PROJW + c] = acc[i][j] + g_bcat[c];
        }
    }
}

// ---------------- K4: f[b,n,e] = theta . phi[nbr] + column sumsq -----------
__global__ void k_f() {
    int bi = blockIdx.x;                    // b*4096+n
    int b = bi >> 12, n = bi & 4095;
    int tid = threadIdx.x;                  // blockDim = 64
    __shared__ float th[64];
    th[tid] = g_proj[bi * PROJW + tid];     // theta part (cols 0..63)
    __syncthreads();
    if (tid < EDIM) {
        int i = n >> 8, j = (n >> 4) & 15, k = n & 15;
        int m = nbr_idx(i, j, k, tid);
        const float4* ph4 = reinterpret_cast<const float4*>(
            &g_proj[((b << 12) + m) * PROJW + 64]);   // phi part
        float acc = 0.f;
#pragma unroll
        for (int d = 0; d < 16; d++) {
            float4 v = ph4[d];
            acc += th[4 * d] * v.x + th[4 * d + 1] * v.y + th[4 * d + 2] * v.z + th[4 * d + 3] * v.w;
        }
        g_f[bi * EDIM + tid] = acc;
        atomicAdd(&g_ss[(b * 46 + tid) * 32], acc * acc);
    }
}

// ---------------- K5: softmax + neighbor aggregate + r-proj + residual -----
__global__ void k_attn(const float* __restrict__ r_w, const float* __restrict__ r_b,
                       float* __restrict__ d_out, int last) {
    int bi = blockIdx.x;
    int b = bi >> 12, n = bi & 4095;
    int tid = threadIdx.x;                  // blockDim = 128
    __shared__ float s[64];
    __shared__ float y[64];
    __shared__ int nb[EDIM];
    __shared__ float red;

    int i = n >> 8, j = (n >> 4) & 15, k = n & 15;
    if (tid < EDIM) {
        nb[tid] = nbr_idx(i, j, k, tid);
        float fv = g_f[bi * EDIM + tid] / (1e-6f + sqrtf(g_ss[(b * 46 + tid) * 32]));
        float fpv = g_fp[n * EDIM + tid] / (1e-6f + sqrtf(g_ssfp[tid * 32]));
        s[tid] = fv + fmaxf(fpv, 0.f);
    } else if (tid < 64) {
        s[tid] = -1e30f;
    }
    __syncthreads();
    if (tid < 32) {
        float v = fmaxf(s[tid], s[tid + 32]);
#pragma unroll
        for (int o = 16; o; o >>= 1) v = fmaxf(v, __shfl_xor_sync(0xffffffffu, v, o));
        if (tid == 0) red = v;
    }
    __syncthreads();
    float mx = red;
    if (tid < 64) s[tid] = expf(s[tid] - mx);
    __syncthreads();
    if (tid < 32) {
        float v = s[tid] + s[tid + 32];
#pragma unroll
        for (int o = 16; o; o >>= 1) v += __shfl_xor_sync(0xffffffffu, v, o);
        if (tid == 0) red = v;
    }
    __syncthreads();
    float inv = 1.f / red;

    if (tid < 64) {
        float acc = 0.f;
#pragma unroll 2
        for (int e = 0; e < EDIM; e++)
            acc += s[e] * g_proj[((b << 12) + nb[e]) * PROJW + 128 + tid];  // G part
        y[tid] = acc * inv;
    }
    __syncthreads();
    {
        float acc = r_b[tid];
        const float4* rw4 = reinterpret_cast<const float4*>(r_w + tid * 64);
#pragma unroll
        for (int g4 = 0; g4 < 16; g4++) {
            float4 v = rw4[g4];
            acc += y[4 * g4] * v.x + y[4 * g4 + 1] * v.y + y[4 * g4 + 2] * v.z + y[4 * g4 + 3] * v.w;
        }
        float val = g_h[bi * CDIM + tid] + acc;
        if (last) d_out[(((b << 7) + tid) << 12) + n] = val;   // [B,C,N] transposed
        else g_h[bi * CDIM + tid] = val;
    }
}

// ---------------------------------------------------------------------------
extern "C" void kernel_launch(void* const* d_in, const int* in_sizes, int n_in,
                              void* d_out, int out_size) {
    const float* x    = (const float*)d_in[0];
    const float* G_w  = (const float*)d_in[1];
    const float* G_b  = (const float*)d_in[2];
    const float* th_w = (const float*)d_in[3];
    const float* th_b = (const float*)d_in[4];
    const float* ph_w = (const float*)d_in[5];
    const float* ph_b = (const float*)d_in[6];
    const float* r_w  = (const float*)d_in[7];
    const float* r_b  = (const float*)d_in[8];
    const float* gt_w = (const float*)d_in[9];
    const float* gt_b = (const float*)d_in[10];
    const float* gp_w = (const float*)d_in[11];
    const float* gp_b = (const float*)d_in[12];
    float* out = (float*)d_out;

    k_tr<<<(BCNT * NNODE * CDIM) / 256, 256>>>(x);
    k_prep<<<256, 256>>>(G_w, G_b, th_w, th_b, ph_w, ph_b, gt_w, gt_b, gp_w, gp_b);
    k_fp<<<NNODE, 64>>>();

    for (int r = 0; r < 3; r++) {
        k_proj<<<dim3(128, 3), 256>>>();
        k_f<<<BCNT * NNODE, 64>>>();
        k_attn<<<BCNT * NNODE, 128>>>(r_w, r_b, out, r == 2);
    }
}

// round 3
// speedup vs baseline: 1.4141x; 1.4141x over previous
#include <cuda_runtime.h>

// Fixed shapes: B=2, C=128, D=H=W=16
#define NNODE 4096
#define CDIM  128
#define EDIM  46
#define BCNT  2
#define PROJW 192   // theta(64) | phi(64) | G(64)

// ---------------- scratch (device globals) ---------------------------------
__device__ float g_h[BCNT * NNODE * CDIM];        // [B,N,C]
__device__ float g_proj[BCNT * NNODE * PROJW];    // [B,N,192]
__device__ float g_f[BCNT * NNODE * EDIM];        // raw f
__device__ float g_fp[NNODE * EDIM];              // raw f_p
__device__ float g_pth[NNODE * 64];
__device__ float g_pph[NNODE * 64];
__device__ float g_ss[92 * 32];                   // [B*E] sumsq, 128B stride
__device__ float g_ssfp[46 * 32];                 // [E]   sumsq, 128B stride
__device__ float g_Wcat[PROJW * CDIM];
__device__ float g_bcat[PROJW];
__device__ float g_y[3][BCNT * NNODE * 64];       // per-axis partial aggregates

// line decode: axis0 line=(j,k) step 256; axis1 line=(i,k) step 16; axis2 line=(i,j) step 1
__device__ __forceinline__ void line_decode(int axis, int line,
                                            int& nbase, int& step, int& c0, int& c1) {
    if (axis == 0)      { nbase = line; step = 256; c0 = 0; c1 = 0; }
    else if (axis == 1) { c0 = line >> 4; nbase = (c0 << 8) | (line & 15); step = 16; c1 = 0; }
    else                { c0 = line >> 4; c1 = line & 15; nbase = (c0 << 8) | (c1 << 4); step = 1; }
}
// sorted-list e-position for (own coord v, neighbor coord vp) on given axis
__device__ __forceinline__ int e_pos(int axis, int c0, int c1, int v, int vp) {
    if (axis == 0) return vp < v ? vp : vp + 30;
    if (axis == 1) return c0 + (vp < v ? vp : vp + 15);
    return c0 + c1 + vp;                            // includes self (vp==v)
}

// ---------------- K1: transpose + weight concat + geo + zero ssfp ----------
__global__ void k_prep(const float* __restrict__ x,
                       const float* __restrict__ Gw, const float* __restrict__ Gb,
                       const float* __restrict__ thw, const float* __restrict__ thb,
                       const float* __restrict__ phw, const float* __restrict__ phb,
                       const float* __restrict__ gthw, const float* __restrict__ gthb,
                       const float* __restrict__ gphw, const float* __restrict__ gphb) {
    int gtid = blockIdx.x * blockDim.x + threadIdx.x;
    int gs = gridDim.x * blockDim.x;

    for (int idx = gtid; idx < BCNT * NNODE * CDIM; idx += gs) {
        int b = idx >> 19, rem = idx & ((1 << 19) - 1);
        int n = rem >> 7, c = rem & 127;
        g_h[idx] = x[(((b << 7) + c) << 12) + n];
    }
    for (int idx = gtid; idx < PROJW * CDIM; idx += gs) {
        int r = idx >> 7, k = idx & 127;
        g_Wcat[idx] = (r < 64) ? thw[r * 128 + k]
                    : (r < 128) ? phw[(r - 64) * 128 + k]
                    : Gw[(r - 128) * 128 + k];
    }
    for (int idx = gtid; idx < PROJW; idx += gs)
        g_bcat[idx] = (idx < 64) ? thb[idx] : (idx < 128) ? phb[idx - 64] : Gb[idx - 128];
    for (int idx = gtid; idx < 46; idx += gs) g_ssfp[idx * 32] = 0.f;

    for (int idx = gtid; idx < NNODE * 64; idx += gs) {
        int n = idx >> 6, d = idx & 63;
        int i = n >> 8, j = (n >> 4) & 15, k = n & 15;
        float p0 = i * (1.f / 15.f) - 0.5f;
        float p1 = j * (1.f / 15.f) - 0.5f;
        float p2 = k * (1.f / 15.f) - 0.5f;
        g_pth[idx] = p0 * gthw[d * 3] + p1 * gthw[d * 3 + 1] + p2 * gthw[d * 3 + 2] + gthb[d];
        g_pph[idx] = p0 * gphw[d * 3] + p1 * gphw[d * 3 + 1] + p2 * gphw[d * 3 + 2] + gphb[d];
    }
}

// ---------------- K2: line-Gram kernel (f or f_p) --------------------------
// grid (256 lines, 3 axes, B), block 256. mode 0: f_p from pth/pph; mode 1: f from proj.
__global__ __launch_bounds__(256) void k_gram(int mode) {
    __shared__ __align__(16) float Th[16][68];
    __shared__ __align__(16) float Ph[16][68];
    __shared__ float ssl[46];
    int line = blockIdx.x, axis = blockIdx.y, b = blockIdx.z;
    int t = threadIdx.x;

    const float* thp; const float* php; int stride; float* fOut; float* ssOut;
    if (mode) { thp = g_proj; php = g_proj + 64; stride = PROJW; fOut = g_f; ssOut = g_ss; }
    else      { thp = g_pth;  php = g_pph;       stride = 64;    fOut = g_fp; ssOut = g_ssfp; }
    int bofs = b * NNODE * stride;
    fOut += b * NNODE * EDIM;
    ssOut += b * EDIM * 32;

    int nbase, step, c0, c1;
    line_decode(axis, line, nbase, step, c0, c1);

    if (t < 46) ssl[t] = 0.f;
    {   // coalesced tile load: 16 rows x 64 floats each
        int r = t >> 4, c = t & 15;
        int n = nbase + r * step;
        float4 tv = *(const float4*)(thp + bofs + n * stride + c * 4);
        float4 pv = *(const float4*)(php + bofs + n * stride + c * 4);
        *(float4*)&Th[r][c * 4] = tv;
        *(float4*)&Ph[r][c * 4] = pv;
    }
    __syncthreads();

    int v = t >> 4, vp = t & 15;
    const float4* tr = (const float4*)&Th[v][0];
    const float4* pr = (const float4*)&Ph[vp][0];
    float acc = 0.f;
#pragma unroll
    for (int d = 0; d < 16; d++) {
        float4 a = tr[d], p = pr[d];
        acc += a.x * p.x + a.y * p.y + a.z * p.z + a.w * p.w;
    }
    if (axis == 2 || v != vp) {
        int e = e_pos(axis, c0, c1, v, vp);
        int n = nbase + v * step;
        fOut[n * EDIM + e] = acc;
        atomicAdd(&ssl[e], acc * acc);
    }
    __syncthreads();
    if (t < 46) { float s = ssl[t]; if (s != 0.f) atomicAdd(&ssOut[t * 32], s); }
}

// ---------------- K3: fused projection GEMM [8192,128]@[128,192]+bias ------
__global__ void k_proj() {
    __shared__ float As[64][33];
    __shared__ float Bs[32][68];
    int tid = threadIdx.x;
    if (blockIdx.x == 0 && blockIdx.y == 0 && tid < 92) g_ss[tid * 32] = 0.f;

    int rowBase = blockIdx.x * 64;
    int colBase = blockIdx.y * 64;
    int tx = tid & 15, ty = tid >> 4;
    float acc[4][4] = {};

    for (int k0 = 0; k0 < 128; k0 += 32) {
        for (int idx = tid; idx < 64 * 32; idx += 256) {
            int r = idx >> 5, kk = idx & 31;
            As[r][kk] = g_h[(rowBase + r) * 128 + k0 + kk];
        }
        for (int idx = tid; idx < 32 * 64; idx += 256) {
            int c = idx >> 5, kk = idx & 31;
            Bs[kk][c] = g_Wcat[(colBase + c) * 128 + k0 + kk];
        }
        __syncthreads();
#pragma unroll
        for (int kk = 0; kk < 32; kk++) {
            float a[4], bb[4];
#pragma unroll
            for (int i = 0; i < 4; i++) a[i] = As[ty * 4 + i][kk];
#pragma unroll
            for (int j = 0; j < 4; j++) bb[j] = Bs[kk][tx * 4 + j];
#pragma unroll
            for (int i = 0; i < 4; i++)
#pragma unroll
                for (int j = 0; j < 4; j++) acc[i][j] += a[i] * bb[j];
        }
        __syncthreads();
    }
#pragma unroll
    for (int i = 0; i < 4; i++)
#pragma unroll
        for (int j = 0; j < 4; j++) {
            int c = colBase + tx * 4 + j;
            g_proj[(rowBase + ty * 4 + i) * PROJW + c] = acc[i][j] + g_bcat[c];
        }
}

// ---------------- K4: per-line softmax + aggregate -> g_y[axis] ------------
// grid (256, 3, B), block 256 (ty=node-in-line, tx=16 g-chunks)
__global__ __launch_bounds__(256) void k_agg() {
    __shared__ __align__(16) float Gs[16][68];
    __shared__ float fs[16][48];
    __shared__ float nrm[46], nfp[46];
    int line = blockIdx.x, axis = blockIdx.y, b = blockIdx.z;
    int t = threadIdx.x;

    int nbase, step, c0, c1;
    line_decode(axis, line, nbase, step, c0, c1);

    if (t < 46) {
        nrm[t] = 1.f / (1e-6f + sqrtf(g_ss[(b * 46 + t) * 32]));
        nfp[t] = 1.f / (1e-6f + sqrtf(g_ssfp[t * 32]));
    }
    {   // coalesced G tile load (cols 128..191 of proj)
        int r = t >> 4, c = t & 15;
        int n = nbase + r * step;
        *(float4*)&Gs[r][c * 4] =
            *(const float4*)(g_proj + (b * NNODE + n) * PROJW + 128 + c * 4);
    }
    __syncthreads();

    for (int l = t; l < 16 * 48; l += 256) {
        int nd = l / 48, e = l - nd * 48;
        float s = -1e30f;
        if (e < 46) {
            int n = nbase + nd * step;
            float fv  = g_f[(b * NNODE + n) * EDIM + e] * nrm[e];
            float fpv = g_fp[n * EDIM + e] * nfp[e];
            s = fv + fmaxf(fpv, 0.f);
        }
        fs[nd][e] = s;
    }
    __syncthreads();

    int ty = t >> 4, tx = t & 15;
    float a0 = fs[ty][tx], a1 = fs[ty][tx + 16], a2 = fs[ty][tx + 32];
    float m = fmaxf(a0, fmaxf(a1, a2));
#pragma unroll
    for (int o = 8; o; o >>= 1) m = fmaxf(m, __shfl_xor_sync(0xffffffffu, m, o));
    float e0 = expf(a0 - m), e1 = expf(a1 - m), e2 = expf(a2 - m);  // pads exp->0
    float z = e0 + e1 + e2;
#pragma unroll
    for (int o = 8; o; o >>= 1) z += __shfl_xor_sync(0xffffffffu, z, o);
    float invZ = 1.f / z;
    fs[ty][tx] = e0; fs[ty][tx + 16] = e1; fs[ty][tx + 32] = e2;
    __syncwarp();

    float4 acc = {0.f, 0.f, 0.f, 0.f};
#pragma unroll
    for (int vp = 0; vp < 16; vp++) {
        float w;
        if (axis == 2)      w = fs[ty][c0 + c1 + vp];
        else if (vp == ty)  w = 0.f;
        else if (axis == 0) w = fs[ty][vp < ty ? vp : vp + 30];
        else                w = fs[ty][c0 + (vp < ty ? vp : vp + 15)];
        float4 g = *(const float4*)&Gs[vp][tx * 4];
        acc.x += w * g.x; acc.y += w * g.y; acc.z += w * g.z; acc.w += w * g.w;
    }
    acc.x *= invZ; acc.y *= invZ; acc.z *= invZ; acc.w *= invZ;
    int n = nbase + ty * step;
    *(float4*)&g_y[axis][(b * NNODE + n) * 64 + tx * 4] = acc;
}

// ---------------- K5: y-sum + r-proj + residual ----------------------------
__global__ __launch_bounds__(128) void k_resid(const float* __restrict__ r_w,
                                               const float* __restrict__ r_b,
                                               float* __restrict__ d_out, int last) {
    int bi = blockIdx.x;                    // b*4096+n
    int tid = threadIdx.x;
    __shared__ float y[64];
    if (tid < 64) {
        int o = bi * 64 + tid;
        y[tid] = g_y[0][o] + g_y[1][o] + g_y[2][o];
    }
    __syncthreads();
    float acc = r_b[tid];
    const float4* rw4 = reinterpret_cast<const float4*>(r_w + tid * 64);
#pragma unroll
    for (int g4 = 0; g4 < 16; g4++) {
        float4 v = rw4[g4];
        acc += y[4 * g4] * v.x + y[4 * g4 + 1] * v.y + y[4 * g4 + 2] * v.z + y[4 * g4 + 3] * v.w;
    }
    float val = g_h[bi * CDIM + tid] + acc;
    if (last) {
        int b = bi >> 12, n = bi & 4095;
        d_out[(((b << 7) + tid) << 12) + n] = val;
    } else {
        g_h[bi * CDIM + tid] = val;
    }
}

// ---------------------------------------------------------------------------
extern "C" void kernel_launch(void* const* d_in, const int* in_sizes, int n_in,
                              void* d_out, int out_size) {
    const float* x    = (const float*)d_in[0];
    const float* G_w  = (const float*)d_in[1];
    const float* G_b  = (const float*)d_in[2];
    const float* th_w = (const float*)d_in[3];
    const float* th_b = (const float*)d_in[4];
    const float* ph_w = (const float*)d_in[5];
    const float* ph_b = (const float*)d_in[6];
    const float* r_w  = (const float*)d_in[7];
    const float* r_b  = (const float*)d_in[8];
    const float* gt_w = (const float*)d_in[9];
    const float* gt_b = (const float*)d_in[10];
    const float* gp_w = (const float*)d_in[11];
    const float* gp_b = (const float*)d_in[12];
    float* out = (float*)d_out;

    k_prep<<<256, 256>>>(x, G_w, G_b, th_w, th_b, ph_w, ph_b, gt_w, gt_b, gp_w, gp_b);
    k_gram<<<dim3(256, 3, 1), 256>>>(0);                     // f_p lines

    for (int r = 0; r < 3; r++) {
        k_proj<<<dim3(128, 3), 256>>>();
        k_gram<<<dim3(256, 3, BCNT), 256>>>(1);              // f lines
        k_agg<<<dim3(256, 3, BCNT), 256>>>();
        k_resid<<<BCNT * NNODE, 128>>>(r_w, r_b, out, r == 2);
    }
}

// round 4
// speedup vs baseline: 2.2132x; 1.5651x over previous
#include <cuda_runtime.h>

// Fixed shapes: B=2, C=128, D=H=W=16
#define NNODE 4096
#define CDIM  128
#define EDIM  46
#define BCNT  2
#define PROJW 192   // theta(64) | phi(64) | G(64)
#define NB    512   // persistent blocks (co-resident: 4/SM x 148 SMs = 592 >= 512)
#define NT    256

// ---------------- scratch (device globals) ---------------------------------
__device__ float g_h[BCNT * NNODE * CDIM];
__device__ float g_proj[BCNT * NNODE * PROJW];
__device__ float g_f[BCNT * NNODE * EDIM];
__device__ float g_fp[NNODE * EDIM];
__device__ float g_pth[NNODE * 64];
__device__ float g_pph[NNODE * 64];
__device__ float g_ss[92 * 32];
__device__ float g_ssfp[46 * 32];
__device__ float g_Wcat[PROJW * CDIM];
__device__ float g_bcat[PROJW];
__device__ float g_y[3][BCNT * NNODE * 64];
__device__ int            g_cnt;
__device__ volatile int   g_sense;

// ---------------- shared memory union ---------------------------------------
struct SmemGemm { float A[32][68]; float B[32][68]; };                    // 17408 B
struct SmemGram { float Th[16][68]; float Ph[16][68]; float ssl[46]; };   //  8888 B
struct SmemAgg  { float Gs[16][68]; float fs[16][48]; float nrm[46]; float nfp[46]; };
union __align__(16) Smem { SmemGemm g; SmemGram r; SmemAgg a; };

// ---------------- grid barrier (sense-reversing) ----------------------------
__device__ __forceinline__ void gsync() {
    __syncthreads();
    if (threadIdx.x == 0) {
        __threadfence();
        int s = g_sense;
        if (atomicAdd(&g_cnt, 1) == NB - 1) {
            g_cnt = 0;
            __threadfence();
            g_sense = s ^ 1;
        } else {
            while (g_sense == s) __nanosleep(64);
        }
        __threadfence();
    }
    __syncthreads();
}

// line decode: axis0 line=(j,k) step 256; axis1 line=(i,k) step 16; axis2 line=(i,j) step 1
__device__ __forceinline__ void line_decode(int axis, int line,
                                            int& nbase, int& step, int& c0, int& c1) {
    if (axis == 0)      { nbase = line; step = 256; c0 = 0; c1 = 0; }
    else if (axis == 1) { c0 = line >> 4; nbase = (c0 << 8) | (line & 15); step = 16; c1 = 0; }
    else                { c0 = line >> 4; c1 = line & 15; nbase = (c0 << 8) | (c1 << 4); step = 1; }
}
// sorted-list e-position for (own coord v, neighbor coord vp)
__device__ __forceinline__ int e_pos(int axis, int c0, int c1, int v, int vp) {
    if (axis == 0) return vp < v ? vp : vp + 30;
    if (axis == 1) return c0 + (vp < v ? vp : vp + 15);
    return c0 + c1 + vp;                          // includes self
}

// ---------------- line-Gram tile ---------------------------------------------
__device__ __forceinline__ void gram_tile(Smem& sm, int line, int axis,
        const float* __restrict__ thp, const float* __restrict__ php, int stride,
        float* __restrict__ fOut, float* __restrict__ ssOut) {
    int t = threadIdx.x;
    int nbase, step, c0, c1;
    line_decode(axis, line, nbase, step, c0, c1);
    if (t < 46) sm.r.ssl[t] = 0.f;
    {
        int r = t >> 4, c = t & 15;
        int n = nbase + r * step;
        *(float4*)&sm.r.Th[r][c * 4] = *(const float4*)(thp + n * stride + c * 4);
        *(float4*)&sm.r.Ph[r][c * 4] = *(const float4*)(php + n * stride + c * 4);
    }
    __syncthreads();
    int v = t >> 4, vp = t & 15;
    const float4* tr = (const float4*)&sm.r.Th[v][0];
    const float4* pr = (const float4*)&sm.r.Ph[vp][0];
    float acc = 0.f;
#pragma unroll
    for (int d = 0; d < 16; d++) {
        float4 a = tr[d], p = pr[d];
        acc += a.x * p.x + a.y * p.y + a.z * p.z + a.w * p.w;
    }
    if (axis == 2 || v != vp) {
        int e = e_pos(axis, c0, c1, v, vp);
        fOut[(nbase + v * step) * EDIM + e] = acc;
        atomicAdd(&sm.r.ssl[e], acc * acc);
    }
    __syncthreads();
    if (t < 46) { float s = sm.r.ssl[t]; if (s != 0.f) atomicAdd(&ssOut[t * 32], s); }
}

// ---------------- 64x64 GEMM tile: g_proj = g_h @ Wcat^T + bcat -------------
__device__ __forceinline__ void proj_tile(Smem& sm, int task) {
    int rowTile = task / 3;
    int rowBase = rowTile << 6, colBase = (task - rowTile * 3) << 6;
    int t = threadIdx.x, tx = t & 15, ty = t >> 4;
    float acc[4][4] = {};
    for (int k0 = 0; k0 < 128; k0 += 32) {
#pragma unroll
        for (int it = 0; it < 2; it++) {
            int idx = t + it * 256;
            int r = idx & 63, k4 = idx >> 6;       // k4 in 0..7
            float4 v = *(const float4*)(g_h + (rowBase + r) * 128 + k0 + k4 * 4);
            sm.g.A[k4 * 4 + 0][r] = v.x; sm.g.A[k4 * 4 + 1][r] = v.y;
            sm.g.A[k4 * 4 + 2][r] = v.z; sm.g.A[k4 * 4 + 3][r] = v.w;
            float4 w = *(const float4*)(g_Wcat + (colBase + r) * 128 + k0 + k4 * 4);
            sm.g.B[k4 * 4 + 0][r] = w.x; sm.g.B[k4 * 4 + 1][r] = w.y;
            sm.g.B[k4 * 4 + 2][r] = w.z; sm.g.B[k4 * 4 + 3][r] = w.w;
        }
        __syncthreads();
#pragma unroll
        for (int kk = 0; kk < 32; kk++) {
            float4 a = *(const float4*)&sm.g.A[kk][ty * 4];
            float4 b = *(const float4*)&sm.g.B[kk][tx * 4];
            float av[4] = {a.x, a.y, a.z, a.w};
            float bv[4] = {b.x, b.y, b.z, b.w};
#pragma unroll
            for (int i = 0; i < 4; i++)
#pragma unroll
                for (int j = 0; j < 4; j++) acc[i][j] += av[i] * bv[j];
        }
        __syncthreads();
    }
#pragma unroll
    for (int i = 0; i < 4; i++) {
        int row = rowBase + ty * 4 + i;
#pragma unroll
        for (int j = 0; j < 4; j++) {
            int c = colBase + tx * 4 + j;
            g_proj[row * PROJW + c] = acc[i][j] + g_bcat[c];
        }
    }
}

// ---------------- per-line softmax + aggregate -> g_y[axis] ------------------
__device__ __forceinline__ void agg_tile(Smem& sm, int line, int axis, int b) {
    int t = threadIdx.x;
    int nbase, step, c0, c1;
    line_decode(axis, line, nbase, step, c0, c1);
    if (t < 46) {
        sm.a.nrm[t] = 1.f / (1e-6f + sqrtf(g_ss[(b * 46 + t) * 32]));
        sm.a.nfp[t] = 1.f / (1e-6f + sqrtf(g_ssfp[t * 32]));
    }
    {
        int r = t >> 4, c = t & 15;
        int n = nbase + r * step;
        *(float4*)&sm.a.Gs[r][c * 4] =
            *(const float4*)(g_proj + (b * NNODE + n) * PROJW + 128 + c * 4);
    }
    __syncthreads();
    for (int l = t; l < 16 * 48; l += 256) {
        int nd = l / 48, e = l - nd * 48;
        float s = -1e30f;
        if (e < 46) {
            int n = nbase + nd * step;
            s = g_f[(b * NNODE + n) * EDIM + e] * sm.a.nrm[e]
              + fmaxf(g_fp[n * EDIM + e] * sm.a.nfp[e], 0.f);
        }
        sm.a.fs[nd][e] = s;
    }
    __syncthreads();
    int ty = t >> 4, tx = t & 15;
    float a0 = sm.a.fs[ty][tx], a1 = sm.a.fs[ty][tx + 16], a2 = sm.a.fs[ty][tx + 32];
    float m = fmaxf(a0, fmaxf(a1, a2));
#pragma unroll
    for (int o = 8; o; o >>= 1) m = fmaxf(m, __shfl_xor_sync(0xffffffffu, m, o));
    float e0 = expf(a0 - m), e1 = expf(a1 - m), e2 = expf(a2 - m);
    float z = e0 + e1 + e2;
#pragma unroll
    for (int o = 8; o; o >>= 1) z += __shfl_xor_sync(0xffffffffu, z, o);
    float invZ = 1.f / z;
    sm.a.fs[ty][tx] = e0; sm.a.fs[ty][tx + 16] = e1; sm.a.fs[ty][tx + 32] = e2;
    __syncwarp();

    float4 acc = {0.f, 0.f, 0.f, 0.f};
#pragma unroll
    for (int vp = 0; vp < 16; vp++) {
        float w;
        if (axis == 2)      w = sm.a.fs[ty][c0 + c1 + vp];
        else if (vp == ty)  w = 0.f;
        else if (axis == 0) w = sm.a.fs[ty][vp < ty ? vp : vp + 30];
        else                w = sm.a.fs[ty][c0 + (vp < ty ? vp : vp + 15)];
        float4 g = *(const float4*)&sm.a.Gs[vp][tx * 4];
        acc.x += w * g.x; acc.y += w * g.y; acc.z += w * g.z; acc.w += w * g.w;
    }
    acc.x *= invZ; acc.y *= invZ; acc.z *= invZ; acc.w *= invZ;
    int n = nbase + ty * step;
    *(float4*)&g_y[axis][(b * NNODE + n) * 64 + tx * 4] = acc;
    __syncthreads();     // protect fs/Gs before next task's loads
}

// ---------------- resid GEMM tile: h += (y0+y1+y2) @ r_w^T + r_b -------------
__device__ __forceinline__ void resid_tile(Smem& sm, int task,
        const float* __restrict__ rw, const float* __restrict__ rb,
        float* __restrict__ outp, int last) {
    int rowBase = (task >> 1) << 6, colBase = (task & 1) << 6;
    int t = threadIdx.x, tx = t & 15, ty = t >> 4;
    const int AX = BCNT * NNODE * 64;
    float acc[4][4] = {};
    for (int k0 = 0; k0 < 64; k0 += 32) {
#pragma unroll
        for (int it = 0; it < 2; it++) {
            int idx = t + it * 256;
            int r = idx & 63, k4 = idx >> 6;
            const float* yb = &g_y[0][(rowBase + r) * 64 + k0 + k4 * 4];
            float4 v0 = *(const float4*)yb;
            float4 v1 = *(const float4*)(yb + AX);
            float4 v2 = *(const float4*)(yb + 2 * AX);
            sm.g.A[k4 * 4 + 0][r] = v0.x + v1.x + v2.x;
            sm.g.A[k4 * 4 + 1][r] = v0.y + v1.y + v2.y;
            sm.g.A[k4 * 4 + 2][r] = v0.z + v1.z + v2.z;
            sm.g.A[k4 * 4 + 3][r] = v0.w + v1.w + v2.w;
            float4 w = *(const float4*)(rw + (colBase + r) * 64 + k0 + k4 * 4);
            sm.g.B[k4 * 4 + 0][r] = w.x; sm.g.B[k4 * 4 + 1][r] = w.y;
            sm.g.B[k4 * 4 + 2][r] = w.z; sm.g.B[k4 * 4 + 3][r] = w.w;
        }
        __syncthreads();
#pragma unroll
        for (int kk = 0; kk < 32; kk++) {
            float4 a = *(const float4*)&sm.g.A[kk][ty * 4];
            float4 b = *(const float4*)&sm.g.B[kk][tx * 4];
            float av[4] = {a.x, a.y, a.z, a.w};
            float bv[4] = {b.x, b.y, b.z, b.w};
#pragma unroll
            for (int i = 0; i < 4; i++)
#pragma unroll
                for (int j = 0; j < 4; j++) acc[i][j] += av[i] * bv[j];
        }
        __syncthreads();
    }
#pragma unroll
    for (int i = 0; i < 4; i++) {
        int row = rowBase + ty * 4 + i;
#pragma unroll
        for (int j = 0; j < 4; j++) {
            int c = colBase + tx * 4 + j;
            float val = acc[i][j] + rb[c] + g_h[row * 128 + c];
            if (last) {
                int b = row >> 12, n = row & 4095;
                outp[(((b << 7) + c) << 12) + n] = val;
            } else {
                g_h[row * 128 + c] = val;
            }
        }
    }
}

// ---------------- the single persistent kernel -------------------------------
__global__ __launch_bounds__(NT, 4) void k_all(
        const float* __restrict__ x,
        const float* __restrict__ Gw, const float* __restrict__ Gb,
        const float* __restrict__ thw, const float* __restrict__ thb,
        const float* __restrict__ phw, const float* __restrict__ phb,
        const float* __restrict__ rw, const float* __restrict__ rb,
        const float* __restrict__ gthw, const float* __restrict__ gthb,
        const float* __restrict__ gphw, const float* __restrict__ gphb,
        float* __restrict__ outp) {
    __shared__ Smem sm;
    const int t = threadIdx.x, bid = blockIdx.x;
    const int gtid = bid * NT + t, gs = NB * NT;

    // ---- phase PREP: transpose, weight concat, geo features ----
    for (int idx = gtid; idx < BCNT * NNODE * CDIM; idx += gs) {
        int b = idx >> 19, rem = idx & ((1 << 19) - 1);
        int n = rem >> 7, c = rem & 127;
        g_h[idx] = x[(((b << 7) + c) << 12) + n];
    }
    for (int idx = gtid; idx < PROJW * CDIM; idx += gs) {
        int r = idx >> 7, k = idx & 127;
        g_Wcat[idx] = (r < 64) ? thw[r * 128 + k]
                    : (r < 128) ? phw[(r - 64) * 128 + k]
                    : Gw[(r - 128) * 128 + k];
    }
    for (int idx = gtid; idx < PROJW; idx += gs)
        g_bcat[idx] = (idx < 64) ? thb[idx] : (idx < 128) ? phb[idx - 64] : Gb[idx - 128];
    for (int idx = gtid; idx < 46; idx += gs) g_ssfp[idx * 32] = 0.f;
    for (int idx = gtid; idx < NNODE * 64; idx += gs) {
        int n = idx >> 6, d = idx & 63;
        int i = n >> 8, j = (n >> 4) & 15, k = n & 15;
        float p0 = i * (1.f / 15.f) - 0.5f;
        float p1 = j * (1.f / 15.f) - 0.5f;
        float p2 = k * (1.f / 15.f) - 0.5f;
        g_pth[idx] = p0 * gthw[d * 3] + p1 * gthw[d * 3 + 1] + p2 * gthw[d * 3 + 2] + gthb[d];
        g_pph[idx] = p0 * gphw[d * 3] + p1 * gphw[d * 3 + 1] + p2 * gphw[d * 3 + 2] + gphb[d];
    }
    gsync();

    // ---- phase FP: geo Gram lines (768 tasks) ----
    for (int task = bid; task < 768; task += NB)
        gram_tile(sm, task & 255, task >> 8, g_pth, g_pph, 64, g_fp, g_ssfp);
    gsync();

    for (int r = 0; r < 3; r++) {
        // ---- phase P: fused projection GEMM (384 tasks) + zero g_ss ----
        if (bid == 0 && t < 92) g_ss[t * 32] = 0.f;
        for (int task = bid; task < 384; task += NB) proj_tile(sm, task);
        gsync();

        // ---- phase G: f Gram lines (1536 tasks) ----
        for (int task = bid; task < 1536; task += NB) {
            int b = task / 768, rem = task - b * 768;
            gram_tile(sm, rem & 255, rem >> 8,
                      g_proj + b * NNODE * PROJW, g_proj + b * NNODE * PROJW + 64, PROJW,
                      g_f + b * NNODE * EDIM, g_ss + b * EDIM * 32);
        }
        gsync();

        // ---- phase A: softmax + aggregate (1536 tasks) ----
        for (int task = bid; task < 1536; task += NB) {
            int b = task / 768, rem = task - b * 768;
            agg_tile(sm, rem & 255, rem >> 8, b);
        }
        gsync();

        // ---- phase R: residual GEMM (256 tasks) ----
        for (int task = bid; task < 256; task += NB)
            resid_tile(sm, task, rw, rb, outp, r == 2);
        if (r < 2) gsync();
    }
}

// ---------------------------------------------------------------------------
extern "C" void kernel_launch(void* const* d_in, const int* in_sizes, int n_in,
                              void* d_out, int out_size) {
    const float* x    = (const float*)d_in[0];
    const float* G_w  = (const float*)d_in[1];
    const float* G_b  = (const float*)d_in[2];
    const float* th_w = (const float*)d_in[3];
    const float* th_b = (const float*)d_in[4];
    const float* ph_w = (const float*)d_in[5];
    const float* ph_b = (const float*)d_in[6];
    const float* r_w  = (const float*)d_in[7];
    const float* r_b  = (const float*)d_in[8];
    const float* gt_w = (const float*)d_in[9];
    const float* gt_b = (const float*)d_in[10];
    const float* gp_w = (const float*)d_in[11];
    const float* gp_b = (const float*)d_in[12];
    float* out = (float*)d_out;

    k_all<<<NB, NT>>>(x, G_w, G_b, th_w, th_b, ph_w, ph_b, r_w, r_b,
                      gt_w, gt_b, gp_w, gp_b, out);
}

// round 5
// speedup vs baseline: 2.3677x; 1.0698x over previous
#include <cuda_runtime.h>
#include <cstdint>

// Fixed shapes: B=2, C=128, D=H=W=16
#define NNODE 4096
#define CDIM  128
#define EDIM  46
#define BCNT  2
#define PROJW 192   // theta(64) | phi(64) | G(64)
#define NB    512
#define NT    256

// ---------------- scratch (device globals) ---------------------------------
__device__ float g_h[BCNT * NNODE * CDIM];
__device__ float g_proj[BCNT * NNODE * PROJW];
__device__ float g_f[BCNT * NNODE * EDIM];
__device__ float g_fp[NNODE * EDIM];
__device__ float g_fpn[NNODE * EDIM];             // relu(l2norm(f_p)) precomputed
__device__ float g_pth[NNODE * 64];
__device__ float g_pph[NNODE * 64];
__device__ float g_ss[92 * 32];
__device__ float g_ssfp[46 * 32];
__device__ float g_Wcat[PROJW * CDIM];
__device__ float g_bcat[PROJW];
__device__ float g_y[3][BCNT * NNODE * 64];
__device__ int            g_cnt;
__device__ volatile int   g_sense;

// ---------------- shared memory union ---------------------------------------
struct SmemProj { float Ah[32][72]; float Al[32][72]; float Bh[32][72]; float Bl[32][72]; }; // 36864B
struct SmemGemm { float A[32][68]; float B[32][68]; };
struct SmemGram { float Th[16][68]; float Ph[16][68]; float ssl[46]; };
struct SmemAgg  { float Gs[16][68]; float fs[16][48]; float nrm2[92]; };
struct SmemTr   { float tile[32][33]; };
union __align__(16) Smem { SmemProj p; SmemGemm g; SmemGram r; SmemAgg a; SmemTr tr; };

// ---------------- grid barrier (sense-reversing) ----------------------------
__device__ __forceinline__ void gsync() {
    __syncthreads();
    if (threadIdx.x == 0) {
        __threadfence();
        int s = g_sense;
        if (atomicAdd(&g_cnt, 1) == NB - 1) {
            g_cnt = 0;
            __threadfence();
            g_sense = s ^ 1;
        } else {
            while (g_sense == s) __nanosleep(32);
        }
        __threadfence();
    }
    __syncthreads();
}

// line decode: axis0 line=(j,k) step 256; axis1 line=(i,k) step 16; axis2 line=(i,j) step 1
__device__ __forceinline__ void line_decode(int axis, int line,
                                            int& nbase, int& step, int& c0, int& c1) {
    if (axis == 0)      { nbase = line; step = 256; c0 = 0; c1 = 0; }
    else if (axis == 1) { c0 = line >> 4; nbase = (c0 << 8) | (line & 15); step = 16; c1 = 0; }
    else                { c0 = line >> 4; c1 = line & 15; nbase = (c0 << 8) | (c1 << 4); step = 1; }
}
__device__ __forceinline__ int e_pos(int axis, int c0, int c1, int v, int vp) {
    if (axis == 0) return vp < v ? vp : vp + 30;
    if (axis == 1) return c0 + (vp < v ? vp : vp + 15);
    return c0 + c1 + vp;                          // includes self
}

// ---------------- 3xTF32 mma helper ------------------------------------------
__device__ __forceinline__ void mma8(float* c, const uint32_t* a, uint32_t b0, uint32_t b1) {
    asm volatile("mma.sync.aligned.m16n8k8.row.col.f32.tf32.tf32.f32 "
                 "{%0,%1,%2,%3},{%4,%5,%6,%7},{%8,%9},{%0,%1,%2,%3};\n"
                 : "+f"(c[0]), "+f"(c[1]), "+f"(c[2]), "+f"(c[3])
                 : "r"(a[0]), "r"(a[1]), "r"(a[2]), "r"(a[3]), "r"(b0), "r"(b1));
}

// ---------------- pipelined line-Gram phase ----------------------------------
__device__ __forceinline__ void gram_phase(Smem& sm, int bid, int ntasks,
        const float* __restrict__ thA, const float* __restrict__ phA,
        int stride, int bStrideIn,
        float* __restrict__ fA, int fBStride,
        float* __restrict__ ssA, int ssBStride) {
    int t = threadIdx.x;
    int r = t >> 4, c = t & 15;
    int task = bid;
    bool have = task < ntasks;
    float4 tv, pv;
    int curNb = 0, curAxis = 0, curC0 = 0, curC1 = 0, curSt = 0, curB = 0;
    if (have) {
        int b = task / 768, lt = task - b * 768;
        int axis = lt >> 8, line = lt & 255;
        int nb_, st, c0, c1; line_decode(axis, line, nb_, st, c0, c1);
        int n = nb_ + r * st;
        tv = *(const float4*)(thA + b * bStrideIn + n * stride + c * 4);
        pv = *(const float4*)(phA + b * bStrideIn + n * stride + c * 4);
        curNb = nb_; curAxis = axis; curC0 = c0; curC1 = c1; curSt = st; curB = b;
    }
    float* prevSs = nullptr;
    while (have) {
        int nb_ = curNb, axis = curAxis, c0 = curC0, c1 = curC1, st = curSt, b = curB;
        __syncthreads();                              // prev compute done
        if (t < 46 && prevSs) { float s = sm.r.ssl[t]; if (s != 0.f) atomicAdd(prevSs + t * 32, s); }
        *(float4*)&sm.r.Th[r][c * 4] = tv;
        *(float4*)&sm.r.Ph[r][c * 4] = pv;
        if (t < 46) sm.r.ssl[t] = 0.f;
        task += NB; have = task < ntasks;
        if (have) {                                   // prefetch next (overlaps compute)
            int b2 = task / 768, lt = task - b2 * 768;
            int axis2 = lt >> 8, line2 = lt & 255;
            int n2b, st2, c02, c12; line_decode(axis2, line2, n2b, st2, c02, c12);
            int n2 = n2b + r * st2;
            tv = *(const float4*)(thA + b2 * bStrideIn + n2 * stride + c * 4);
            pv = *(const float4*)(phA + b2 * bStrideIn + n2 * stride + c * 4);
            curNb = n2b; curAxis = axis2; curC0 = c02; curC1 = c12; curSt = st2; curB = b2;
        }
        __syncthreads();
        int v = r, vp = c;
        const float4* tr4 = (const float4*)&sm.r.Th[v][0];
        const float4* pr4 = (const float4*)&sm.r.Ph[vp][0];
        float acc = 0.f;
#pragma unroll
        for (int d = 0; d < 16; d++) {
            float4 a = tr4[d], p = pr4[d];
            acc += a.x * p.x + a.y * p.y + a.z * p.z + a.w * p.w;
        }
        if (axis == 2 || v != vp) {
            int e = e_pos(axis, c0, c1, v, vp);
            fA[b * fBStride + (nb_ + v * st) * EDIM + e] = acc;
            atomicAdd(&sm.r.ssl[e], acc * acc);
        }
        prevSs = ssA + b * ssBStride;
    }
    __syncthreads();
    if (t < 46 && prevSs) { float s = sm.r.ssl[t]; if (s != 0.f) atomicAdd(prevSs + t * 32, s); }
}

// ---------------- proj phase: 3xTF32 mma, 64x64 tiles ------------------------
__device__ __forceinline__ void proj_phase(Smem& sm, int bid) {
    int t = threadIdx.x;
    int lane = t & 31, w = t >> 5;
    int g = lane >> 2, tg = lane & 3;
    int mrow = (w & 3) << 4;          // warp m-offset within 64
    int nb = (w >> 2) << 5;           // warp n-offset within 64
    for (int task = bid; task < 384; task += NB) {
        int rowTile = task / 3;
        int rowBase = rowTile << 6, colBase = (task - rowTile * 3) << 6;
        float acc[4][4];
#pragma unroll
        for (int i = 0; i < 4; i++)
#pragma unroll
            for (int j = 0; j < 4; j++) acc[i][j] = 0.f;

        for (int k0 = 0; k0 < 128; k0 += 32) {
            __syncthreads();
#pragma unroll
            for (int it = 0; it < 2; it++) {
                int idx = t + it * 256;
                int rr = idx & 63, k4 = idx >> 6;
                float4 va = *(const float4*)(g_h + (rowBase + rr) * 128 + k0 + k4 * 4);
                float4 vb = *(const float4*)(g_Wcat + (colBase + rr) * 128 + k0 + k4 * 4);
                const float* vaf = (const float*)&va;
                const float* vbf = (const float*)&vb;
#pragma unroll
                for (int jj = 0; jj < 4; jj++) {
                    float av = vaf[jj];
                    float ah = __uint_as_float(__float_as_uint(av) & 0xFFFFE000u);
                    sm.p.Ah[k4 * 4 + jj][rr] = ah;
                    sm.p.Al[k4 * 4 + jj][rr] = av - ah;
                    float bv = vbf[jj];
                    float bh = __uint_as_float(__float_as_uint(bv) & 0xFFFFE000u);
                    sm.p.Bh[k4 * 4 + jj][rr] = bh;
                    sm.p.Bl[k4 * 4 + jj][rr] = bv - bh;
                }
            }
            __syncthreads();
#pragma unroll
            for (int ks = 0; ks < 4; ks++) {
                int kr = ks * 8;
                uint32_t ah[4], al[4];
                ah[0] = __float_as_uint(sm.p.Ah[kr + tg][mrow + g]);
                ah[1] = __float_as_uint(sm.p.Ah[kr + tg][mrow + g + 8]);
                ah[2] = __float_as_uint(sm.p.Ah[kr + tg + 4][mrow + g]);
                ah[3] = __float_as_uint(sm.p.Ah[kr + tg + 4][mrow + g + 8]);
                al[0] = __float_as_uint(sm.p.Al[kr + tg][mrow + g]);
                al[1] = __float_as_uint(sm.p.Al[kr + tg][mrow + g + 8]);
                al[2] = __float_as_uint(sm.p.Al[kr + tg + 4][mrow + g]);
                al[3] = __float_as_uint(sm.p.Al[kr + tg + 4][mrow + g + 8]);
#pragma unroll
                for (int ch = 0; ch < 4; ch++) {
                    int nn = nb + ch * 8 + g;
                    uint32_t bh0 = __float_as_uint(sm.p.Bh[kr + tg][nn]);
                    uint32_t bh1 = __float_as_uint(sm.p.Bh[kr + tg + 4][nn]);
                    uint32_t bl0 = __float_as_uint(sm.p.Bl[kr + tg][nn]);
                    uint32_t bl1 = __float_as_uint(sm.p.Bl[kr + tg + 4][nn]);
                    mma8(acc[ch], ah, bh0, bh1);     // hi*hi
                    mma8(acc[ch], ah, bl0, bl1);     // hi*lo
                    mma8(acc[ch], al, bh0, bh1);     // lo*hi
                }
            }
        }
#pragma unroll
        for (int ch = 0; ch < 4; ch++) {
            int col = colBase + nb + ch * 8 + 2 * tg;
            int row = rowBase + mrow + g;
            g_proj[row * PROJW + col]         = acc[ch][0] + g_bcat[col];
            g_proj[row * PROJW + col + 1]     = acc[ch][1] + g_bcat[col + 1];
            g_proj[(row + 8) * PROJW + col]     = acc[ch][2] + g_bcat[col];
            g_proj[(row + 8) * PROJW + col + 1] = acc[ch][3] + g_bcat[col + 1];
        }
    }
}

// ---------------- pipelined agg phase ----------------------------------------
__device__ __forceinline__ void agg_phase(Smem& sm, int bid) {
    int t = threadIdx.x;
    if (t < 92) sm.a.nrm2[t] = 1.f / (1e-6f + sqrtf(g_ss[t * 32]));  // both batches
    int r = t >> 4, c = t & 15;
    int task = bid;                         // 1536 tasks: exactly 3 per block
    float4 gv; float fv[3], qv[3]; int lnd[3], le[3];
    int curNb, curAxis, curC0, curC1, curSt, curB;
    {
        int b = task / 768, lt = task - b * 768;
        int axis = lt >> 8, line = lt & 255;
        int nb_, st, c0, c1; line_decode(axis, line, nb_, st, c0, c1);
        gv = *(const float4*)(g_proj + (b * NNODE + nb_ + r * st) * PROJW + 128 + c * 4);
#pragma unroll
        for (int ii = 0; ii < 3; ii++) {
            int l = t + ii * 256; int nd = l / 48, e = l - nd * 48;
            lnd[ii] = nd; le[ii] = e;
            if (e < 46) {
                int n = nb_ + nd * st;
                fv[ii] = g_f[(b * NNODE + n) * EDIM + e];
                qv[ii] = g_fpn[n * EDIM + e];
            }
        }
        curNb = nb_; curAxis = axis; curC0 = c0; curC1 = c1; curSt = st; curB = b;
    }
    bool have = true;
    while (have) {
        int nb_ = curNb, axis = curAxis, c0 = curC0, c1 = curC1, st = curSt, b = curB;
        __syncthreads();                    // prev compute done; nrm2 visible
        *(float4*)&sm.a.Gs[r][c * 4] = gv;
#pragma unroll
        for (int ii = 0; ii < 3; ii++)
            sm.a.fs[lnd[ii]][le[ii]] = (le[ii] < 46)
                ? fv[ii] * sm.a.nrm2[b * 46 + le[ii]] + qv[ii] : -1e30f;
        task += NB; have = task < 1536;
        if (have) {                         // prefetch next
            int b2 = task / 768, lt = task - b2 * 768;
            int axis2 = lt >> 8, line2 = lt & 255;
            int n2b, st2, c02, c12; line_decode(axis2, line2, n2b, st2, c02, c12);
            gv = *(const float4*)(g_proj + (b2 * NNODE + n2b + r * st2) * PROJW + 128 + c * 4);
#pragma unroll
            for (int ii = 0; ii < 3; ii++) {
                if (le[ii] < 46) {
                    int n = n2b + lnd[ii] * st2;
                    fv[ii] = g_f[(b2 * NNODE + n) * EDIM + le[ii]];
                    qv[ii] = g_fpn[n * EDIM + le[ii]];
                }
            }
            curNb = n2b; curAxis = axis2; curC0 = c02; curC1 = c12; curSt = st2; curB = b2;
        }
        __syncthreads();
        int ty = r, tx = c;
        float a0 = sm.a.fs[ty][tx], a1 = sm.a.fs[ty][tx + 16], a2 = sm.a.fs[ty][tx + 32];
        float m = fmaxf(a0, fmaxf(a1, a2));
#pragma unroll
        for (int o = 8; o; o >>= 1) m = fmaxf(m, __shfl_xor_sync(0xffffffffu, m, o));
        float e0 = expf(a0 - m), e1 = expf(a1 - m), e2 = expf(a2 - m);
        float z = e0 + e1 + e2;
#pragma unroll
        for (int o = 8; o; o >>= 1) z += __shfl_xor_sync(0xffffffffu, z, o);
        float invZ = 1.f / z;
        sm.a.fs[ty][tx] = e0; sm.a.fs[ty][tx + 16] = e1; sm.a.fs[ty][tx + 32] = e2;
        __syncwarp();

        float4 acc = {0.f, 0.f, 0.f, 0.f};
#pragma unroll
        for (int vp = 0; vp < 16; vp++) {
            float w;
            if (axis == 2)      w = sm.a.fs[ty][c0 + c1 + vp];
            else if (vp == ty)  w = 0.f;
            else if (axis == 0) w = sm.a.fs[ty][vp < ty ? vp : vp + 30];
            else                w = sm.a.fs[ty][c0 + (vp < ty ? vp : vp + 15)];
            float4 gg = *(const float4*)&sm.a.Gs[vp][tx * 4];
            acc.x += w * gg.x; acc.y += w * gg.y; acc.z += w * gg.z; acc.w += w * gg.w;
        }
        acc.x *= invZ; acc.y *= invZ; acc.z *= invZ; acc.w *= invZ;
        int n = nb_ + ty * st;
        *(float4*)&g_y[axis][(b * NNODE + n) * 64 + tx * 4] = acc;
    }
}

// ---------------- resid GEMM tile (scalar FFMA; small) -----------------------
__device__ __forceinline__ void resid_tile(Smem& sm, int task,
        const float* __restrict__ rw, const float* __restrict__ rb,
        float* __restrict__ outp, int last) {
    int rowBase = (task >> 1) << 6, colBase = (task & 1) << 6;
    int t = threadIdx.x, tx = t & 15, ty = t >> 4;
    const int AX = BCNT * NNODE * 64;
    float acc[4][4] = {};
    for (int k0 = 0; k0 < 64; k0 += 32) {
#pragma unroll
        for (int it = 0; it < 2; it++) {
            int idx = t + it * 256;
            int r = idx & 63, k4 = idx >> 6;
            const float* yb = &g_y[0][(rowBase + r) * 64 + k0 + k4 * 4];
            float4 v0 = *(const float4*)yb;
            float4 v1 = *(const float4*)(yb + AX);
            float4 v2 = *(const float4*)(yb + 2 * AX);
            sm.g.A[k4 * 4 + 0][r] = v0.x + v1.x + v2.x;
            sm.g.A[k4 * 4 + 1][r] = v0.y + v1.y + v2.y;
            sm.g.A[k4 * 4 + 2][r] = v0.z + v1.z + v2.z;
            sm.g.A[k4 * 4 + 3][r] = v0.w + v1.w + v2.w;
            float4 w = *(const float4*)(rw + (colBase + r) * 64 + k0 + k4 * 4);
            sm.g.B[k4 * 4 + 0][r] = w.x; sm.g.B[k4 * 4 + 1][r] = w.y;
            sm.g.B[k4 * 4 + 2][r] = w.z; sm.g.B[k4 * 4 + 3][r] = w.w;
        }
        __syncthreads();
#pragma unroll
        for (int kk = 0; kk < 32; kk++) {
            float4 a = *(const float4*)&sm.g.A[kk][ty * 4];
            float4 b = *(const float4*)&sm.g.B[kk][tx * 4];
            float av[4] = {a.x, a.y, a.z, a.w};
            float bv[4] = {b.x, b.y, b.z, b.w};
#pragma unroll
            for (int i = 0; i < 4; i++)
#pragma unroll
                for (int j = 0; j < 4; j++) acc[i][j] += av[i] * bv[j];
        }
        __syncthreads();
    }
#pragma unroll
    for (int i = 0; i < 4; i++) {
        int row = rowBase + ty * 4 + i;
#pragma unroll
        for (int j = 0; j < 4; j++) {
            int c = colBase + tx * 4 + j;
            float val = acc[i][j] + rb[c] + g_h[row * 128 + c];
            if (last) {
                int b = row >> 12, n = row & 4095;
                outp[(((b << 7) + c) << 12) + n] = val;
            } else {
                g_h[row * 128 + c] = val;
            }
        }
    }
}

// ---------------- the single persistent kernel -------------------------------
__global__ __launch_bounds__(NT, 4) void k_all(
        const float* __restrict__ x,
        const float* __restrict__ Gw, const float* __restrict__ Gb,
        const float* __restrict__ thw, const float* __restrict__ thb,
        const float* __restrict__ phw, const float* __restrict__ phb,
        const float* __restrict__ rw, const float* __restrict__ rb,
        const float* __restrict__ gthw, const float* __restrict__ gthb,
        const float* __restrict__ gphw, const float* __restrict__ gphb,
        float* __restrict__ outp) {
    __shared__ Smem sm;
    const int t = threadIdx.x, bid = blockIdx.x;
    const int gtid = bid * NT + t, gs = NB * NT;

    // ---- phase PREP ----
    // coalesced transpose via 32x32 smem tiles: 1024 tiles
    for (int task = bid; task < 1024; task += NB) {
        int b = task >> 9, ct = (task >> 7) & 3, nt = task & 127;
        __syncthreads();
        for (int l = t; l < 1024; l += NT) {
            int cc = l >> 5, nn = l & 31;
            sm.tr.tile[cc][nn] = x[(((b << 7) + (ct << 5) + cc) << 12) + (nt << 5) + nn];
        }
        __syncthreads();
        for (int l = t; l < 1024; l += NT) {
            int cc = l & 31, nn = l >> 5;
            g_h[(((b << 12) + (nt << 5) + nn) << 7) + (ct << 5) + cc] = sm.tr.tile[cc][nn];
        }
    }
    for (int idx = gtid; idx < PROJW * CDIM; idx += gs) {
        int r = idx >> 7, k = idx & 127;
        g_Wcat[idx] = (r < 64) ? thw[r * 128 + k]
                    : (r < 128) ? phw[(r - 64) * 128 + k]
                    : Gw[(r - 128) * 128 + k];
    }
    for (int idx = gtid; idx < PROJW; idx += gs)
        g_bcat[idx] = (idx < 64) ? thb[idx] : (idx < 128) ? phb[idx - 64] : Gb[idx - 128];
    for (int idx = gtid; idx < 46; idx += gs) g_ssfp[idx * 32] = 0.f;
    for (int idx = gtid; idx < NNODE * 64; idx += gs) {
        int n = idx >> 6, d = idx & 63;
        int i = n >> 8, j = (n >> 4) & 15, k = n & 15;
        float p0 = i * (1.f / 15.f) - 0.5f;
        float p1 = j * (1.f / 15.f) - 0.5f;
        float p2 = k * (1.f / 15.f) - 0.5f;
        g_pth[idx] = p0 * gthw[d * 3] + p1 * gthw[d * 3 + 1] + p2 * gthw[d * 3 + 2] + gthb[d];
        g_pph[idx] = p0 * gphw[d * 3] + p1 * gphw[d * 3 + 1] + p2 * gphw[d * 3 + 2] + gphb[d];
    }
    gsync();

    // ---- phase FP: geo Gram lines ----
    gram_phase(sm, bid, 768, g_pth, g_pph, 64, 0, g_fp, 0, g_ssfp, 0);
    gsync();

    // ---- phase FPN: normalized relu'd f_p ----
    for (int idx = gtid; idx < NNODE * EDIM; idx += gs) {
        int e = idx % EDIM;
        g_fpn[idx] = fmaxf(g_fp[idx] / (1e-6f + sqrtf(g_ssfp[e * 32])), 0.f);
    }
    gsync();

    for (int r = 0; r < 3; r++) {
        // ---- phase P: fused projection GEMM (3xTF32 mma) + zero g_ss ----
        if (bid == 0 && t < 92) g_ss[t * 32] = 0.f;
        proj_phase(sm, bid);
        gsync();

        // ---- phase G: f Gram lines ----
        gram_phase(sm, bid, 1536, g_proj, g_proj + 64, PROJW, NNODE * PROJW,
                   g_f, NNODE * EDIM, g_ss, EDIM * 32);
        gsync();

        // ---- phase A: softmax + aggregate ----
        agg_phase(sm, bid);
        gsync();

        // ---- phase R: residual GEMM ----
        for (int task = bid; task < 256; task += NB)
            resid_tile(sm, task, rw, rb, outp, r == 2);
        if (r < 2) gsync();
    }
}

// ---------------------------------------------------------------------------
extern "C" void kernel_launch(void* const* d_in, const int* in_sizes, int n_in,
                              void* d_out, int out_size) {
    const float* x    = (const float*)d_in[0];
    const float* G_w  = (const float*)d_in[1];
    const float* G_b  = (const float*)d_in[2];
    const float* th_w = (const float*)d_in[3];
    const float* th_b = (const float*)d_in[4];
    const float* ph_w = (const float*)d_in[5];
    const float* ph_b = (const float*)d_in[6];
    const float* r_w  = (const float*)d_in[7];
    const float* r_b  = (const float*)d_in[8];
    const float* gt_w = (const float*)d_in[9];
    const float* gt_b = (const float*)d_in[10];
    const float* gp_w = (const float*)d_in[11];
    const float* gp_b = (const float*)d_in[12];
    float* out = (float*)d_out;

    k_all<<<NB, NT>>>(x, G_w, G_b, th_w, th_b, ph_w, ph_b, r_w, r_b,
                      gt_w, gt_b, gp_w, gp_b, out);
}